// round 6
// baseline (speedup 1.0000x reference)
#include <cuda_runtime.h>
#include <math.h>

#define MAXB 32
#define MAXP 24564
#define MAXO 32
#define LTILE 64             // rows per k_loss block
#define LTHREADS 256         // 4 threads per row
#define MTPB 1024
#define MVPT 24              // ceil(24564/1024)

// ---------------- scratch (zero-initialized at load; self-cleaning) -----------
__device__ int                d_m  [MAXB * MAXP];    // idx | (pos?32:0)
__device__ float              d_lc [MAXB * MAXP];    // negative CE (0 for positives)
__device__ unsigned long long d_bp [MAXB * MAXO];    // (iou_bits, ~p) best prior per truth
__device__ double             g_loss_l;
__device__ double             g_loss_c;
__device__ int                g_num_pos[MAXB];
__device__ int                g_done;

// ---------------- helpers ------------------------------------------------------
__device__ __forceinline__ unsigned int su32(const void* p) {
    unsigned int a;
    asm("{ .reg .u64 t; cvta.to.shared.u64 t, %1; cvt.u32.u64 %0, t; }" : "=r"(a) : "l"(p));
    return a;
}
__device__ __forceinline__ void mbar_init(unsigned int mbar, unsigned int cnt) {
    asm volatile("mbarrier.init.shared.b64 [%0], %1;" :: "r"(mbar), "r"(cnt) : "memory");
}
__device__ __forceinline__ void mbar_expect_tx(unsigned int mbar, unsigned int bytes) {
    asm volatile("mbarrier.arrive.expect_tx.shared.b64 _, [%0], %1;" :: "r"(mbar), "r"(bytes) : "memory");
}
__device__ __forceinline__ void bulk_g2s(unsigned int dst, const void* src,
                                         unsigned int bytes, unsigned int mbar) {
    asm volatile(
        "cp.async.bulk.shared::cta.global.mbarrier::complete_tx::bytes [%0], [%1], %2, [%3];"
        :: "r"(dst), "l"(src), "r"(bytes), "r"(mbar) : "memory");
}
__device__ __forceinline__ void mbar_wait(unsigned int mbar, unsigned int parity) {
    asm volatile(
        "{\n\t"
        ".reg .pred P1;\n\t"
        "WL%=:\n\t"
        "mbarrier.try_wait.parity.acquire.cta.shared::cta.b64 P1, [%0], %1, 0x989680;\n\t"
        "@P1 bra.uni WD%=;\n\t"
        "bra.uni WL%=;\n\t"
        "WD%=:\n\t"
        "}"
        :: "r"(mbar), "r"(parity) : "memory");
}

// ---------------- matching ------------------------------------------------------
__global__ __launch_bounds__(256) void k_match(
    const float* __restrict__ priors, const float* __restrict__ boxes,
    int B, int P, int O)
{
    int b = blockIdx.y;
    int p = blockIdx.x * blockDim.x + threadIdx.x;
    bool valid = (p < P);
    int  pc = valid ? p : (P - 1);

    __shared__ float tb[MAXO * 4];
    if (threadIdx.x < O * 4) tb[threadIdx.x] = boxes[(size_t)b * O * 4 + threadIdx.x];
    __syncthreads();

    float4 pr = ((const float4*)priors)[pc];
    float ax0 = pr.x - pr.z * 0.5f, ay0 = pr.y - pr.w * 0.5f;
    float ax1 = pr.x + pr.z * 0.5f, ay1 = pr.y + pr.w * 0.5f;
    float area_a = (ax1 - ax0) * (ay1 - ay0);

    float best = -1.0f; int bidx = 0;
    #pragma unroll 8
    for (int o = 0; o < O; o++) {
        float bx0 = tb[o*4+0], by0 = tb[o*4+1], bx1 = tb[o*4+2], by1 = tb[o*4+3];
        float lx = fmaxf(ax0, bx0), ly = fmaxf(ay0, by0);
        float rx = fminf(ax1, bx1), ry = fminf(ay1, by1);
        float w = fmaxf(rx - lx, 0.0f), h = fmaxf(ry - ly, 0.0f);
        float inter = w * h;
        float area_b = (bx1 - bx0) * (by1 - by0);
        float iou = inter / (area_a + area_b - inter);
        if (valid && iou > best) { best = iou; bidx = o; }   // first-max (JAX argmax)
        unsigned int kb = valid ? __float_as_uint(iou) : 0u;  // iou >= 0 -> monotone
        unsigned int wmax = __reduce_max_sync(0xffffffffu, kb);
        if (valid && kb == wmax) {
            unsigned long long key =
                (((unsigned long long)kb) << 32) |
                (unsigned long long)(0xFFFFFFFFu - (unsigned)p);
            atomicMax(&d_bp[b * O + o], key);
        }
    }
    if (valid)
        d_m[(size_t)b * P + p] = bidx | ((best >= 0.5f) ? 32 : 0);
}

// ---------------- loss: bulk-async staged tile, quad-per-row ---------------------
__device__ __forceinline__ float sl1(float x) {
    float d = fabsf(x);
    return (d < 1.0f) ? 0.5f * d * d : d - 0.5f;
}

__global__ __launch_bounds__(LTHREADS, 8) void k_loss(
    const float* __restrict__ loc, const float* __restrict__ conf,
    const float* __restrict__ priors, const float* __restrict__ boxes,
    const int* __restrict__ labels, int B, int P, int O, int C)
{
    extern __shared__ float sh[];                    // LTILE*C floats
    __shared__ __align__(8) unsigned long long mbar;
    __shared__ int sbp_p[MAXO];
    __shared__ int slab [MAXO];

    int b  = blockIdx.y;
    int p0 = blockIdx.x * LTILE;
    int t  = threadIdx.x;
    int nrow = min(LTILE, P - p0);

    size_t srcOff = ((size_t)b * P + p0) * (size_t)C;
    const float* src = conf + srcOff;
    unsigned int bytes = (unsigned int)(nrow * C) * 4u;
    bool bulk_ok = ((bytes & 15u) == 0u) && (((srcOff * 4u) & 15u) == 0u);  // uniform

    unsigned int mb = su32(&mbar);
    if (bulk_ok && t == 0) mbar_init(mb, 1);
    __syncthreads();
    if (bulk_ok) {
        if (t == 0) {
            mbar_expect_tx(mb, bytes);
            bulk_g2s(su32(sh), src, bytes, mb);
        }
    } else {
        for (int i = t; i < nrow * C; i += LTHREADS) sh[i] = src[i];
    }
    if (t < O) {   // overlapped with the bulk copy
        unsigned long long key = d_bp[b * O + t];
        sbp_p[t] = (int)(0xFFFFFFFFu - (unsigned)(key & 0xFFFFFFFFull));
        slab [t] = labels[b * O + t];
    }
    if (bulk_ok) mbar_wait(mb, 0);
    __syncthreads();

    // quad-per-row exp sums
    int r = t >> 2, q = t & 3;
    int h = (C + 3) >> 2;
    int c0 = q * h, c1 = min(c0 + h, C);
    float s0 = 0.f, s1 = 0.f, s2 = 0.f, s3 = 0.f;
    if (r < nrow) {
        const float* row = sh + r * C;
        int c = c0;
        for (; c + 3 < c1; c += 4) {
            s0 += __expf(row[c]);   s1 += __expf(row[c+1]);
            s2 += __expf(row[c+2]); s3 += __expf(row[c+3]);
        }
        for (; c < c1; c++) s0 += __expf(row[c]);
    }
    float s = (s0 + s1) + (s2 + s3);
    s += __shfl_xor_sync(0xffffffffu, s, 1);
    s += __shfl_xor_sync(0xffffffffu, s, 2);

    if (q != 0 || r >= nrow) return;
    int p = p0 + r;
    float lse = __logf(s);

    size_t bp = (size_t)b * P + p;
    int m   = d_m[bp];
    int idx = m & 31;
    bool pos = (m & 32) != 0;
    #pragma unroll
    for (int o = 0; o < MAXO; o++)          // sequential -> last writer wins
        if (sbp_p[o] == p) { idx = o; pos = true; }

    int   cls = pos ? slab[idx] : 0;
    float ce  = lse - sh[r * C + cls];
    d_lc[bp] = pos ? 0.0f : ce;
    if (pos) {
        atomicAdd(&g_loss_c, (double)ce);
        atomicAdd(&g_num_pos[b], 1);
        float4 tr = ((const float4*)boxes)[b * O + idx];
        float4 pv = ((const float4*)priors)[p];
        float gx = ((tr.x + tr.z) * 0.5f - pv.x) / (0.1f * pv.z);
        float gy = ((tr.y + tr.w) * 0.5f - pv.y) / (0.1f * pv.w);
        float gw = logf((tr.z - tr.x) / pv.z) / 0.2f;
        float gh = logf((tr.w - tr.y) / pv.w) / 0.2f;
        float4 lp = ((const float4*)loc)[bp];
        float l = sl1(lp.x - gx) + sl1(lp.y - gy) + sl1(lp.z - gw) + sl1(lp.w - gh);
        atomicAdd(&g_loss_l, (double)l);
    }
}

// ---------------- mining: per-warp-hist radix select + finalize + reset ---------
__global__ __launch_bounds__(MTPB) void k_mine(float* out, int B, int P, int O) {
    int b = blockIdx.x;
    const float* lc = d_lc + (size_t)b * P;
    int lane = threadIdx.x & 31;
    int wid  = threadIdx.x >> 5;

    __shared__ unsigned int histw[32 * 256];   // per-warp histograms
    __shared__ unsigned int hist[256];
    __shared__ unsigned int s_prefix;
    __shared__ int s_remaining;
    __shared__ double sred[MTPB / 32];

    // early reset of d_bp for the next replay (k_loss already consumed it)
    if (threadIdx.x < O) d_bp[b * O + threadIdx.x] = 0ull;

    int np = g_num_pos[b];
    long long K64 = 3LL * np;
    if (K64 > P - 1) K64 = P - 1;
    int K = (int)K64;

    if (K > 0) {
        unsigned int keys[MVPT];
        #pragma unroll
        for (int v = 0; v < MVPT; v++) {
            int p = v * MTPB + threadIdx.x;
            keys[v] = (p < P) ? __float_as_uint(lc[p]) : 0u;
        }

        if (threadIdx.x == 0) { s_prefix = 0u; s_remaining = K; }
        __syncthreads();

        for (int pass = 3; pass >= 0; pass--) {
            int shift = pass * 8;
            #pragma unroll
            for (int i = 0; i < 8; i++) histw[i * MTPB + threadIdx.x] = 0u;
            __syncthreads();
            unsigned int prefix = s_prefix;
            #pragma unroll
            for (int v = 0; v < MVPT; v++) {
                int p = v * MTPB + threadIdx.x;
                unsigned int key = keys[v];
                bool match = (p < P) &&
                    ((pass == 3) || ((key >> (shift + 8)) == (prefix >> (shift + 8))));
                unsigned int bin = (key >> shift) & 0xFFu;
                unsigned int grp = __match_any_sync(0xffffffffu, match ? bin : 0x100u);
                if (match && lane == (__ffs(grp) - 1))
                    atomicAdd(&histw[(wid << 8) | bin], __popc(grp));
            }
            __syncthreads();
            if (threadIdx.x < 256) {            // merge per-warp hists (conflict-free)
                unsigned int sum = 0;
                #pragma unroll
                for (int w = 0; w < 32; w++) sum += histw[w * 256 + threadIdx.x];
                hist[threadIdx.x] = sum;
            }
            __syncthreads();
            if (wid == 0) {  // parallel descending scan of 256 bins
                int start = 255 - 8 * lane;
                unsigned int h[8]; unsigned int tot = 0;
                #pragma unroll
                for (int j = 0; j < 8; j++) { h[j] = hist[start - j]; tot += h[j]; }
                unsigned int pre = tot;
                #pragma unroll
                for (int off = 1; off < 32; off <<= 1) {
                    unsigned int tt = __shfl_up_sync(0xffffffffu, pre, off);
                    if (lane >= off) pre += tt;
                }
                pre -= tot;
                unsigned int rem = (unsigned)s_remaining;
                if (pre < rem && pre + tot >= rem) {
                    unsigned int cum = pre;
                    #pragma unroll
                    for (int j = 0; j < 8; j++) {
                        if (cum + h[j] >= rem) {
                            s_prefix = prefix | ((unsigned)(start - j) << shift);
                            s_remaining = (int)(rem - cum);
                            break;
                        }
                        cum += h[j];
                    }
                }
            }
            __syncthreads();
        }

        unsigned int tau = s_prefix;
        int remaining = s_remaining;
        double part = 0.0;
        #pragma unroll
        for (int v = 0; v < MVPT; v++)
            if (keys[v] > tau) part += (double)__uint_as_float(keys[v]);
        #pragma unroll
        for (int off = 16; off; off >>= 1)
            part += __shfl_xor_sync(0xffffffffu, part, off);
        if (lane == 0) sred[wid] = part;
        __syncthreads();
        if (wid == 0) {
            double tt = (lane < MTPB / 32) ? sred[lane] : 0.0;
            #pragma unroll
            for (int off = 16; off; off >>= 1)
                tt += __shfl_xor_sync(0xffffffffu, tt, off);
            if (lane == 0)
                atomicAdd(&g_loss_c, tt + (double)remaining * (double)__uint_as_float(tau));
        }
    }

    // finalize: last block writes the output and resets globals for the next replay
    __syncthreads();
    if (threadIdx.x == 0) {
        __threadfence();
        if (atomicAdd(&g_done, 1) == B - 1) {
            double N = 0.0;
            for (int i = 0; i < B; i++) N += (double)g_num_pos[i];
            float Nf = (float)N;
            out[0] = (float)g_loss_l / Nf + (float)g_loss_c / Nf;
            g_loss_l = 0.0; g_loss_c = 0.0; g_done = 0;
            for (int i = 0; i < B; i++) g_num_pos[i] = 0;
        }
    }
}

// ---------------- launch -----------------------------------------------------------
extern "C" void kernel_launch(void* const* d_in, const int* in_sizes, int n_in,
                              void* d_out, int out_size)
{
    const float* loc    = (const float*)d_in[0];
    const float* conf   = (const float*)d_in[1];
    const float* priors = (const float*)d_in[2];
    const float* boxes  = (const float*)d_in[3];
    const int*   labels = (const int*)  d_in[4];

    int P = in_sizes[2] / 4;
    int B = in_sizes[0] / (P * 4);
    int C = (int)((long long)in_sizes[1] / ((long long)B * P));
    int O = in_sizes[4] / B;

    dim3 g1((P + 255) / 256, B);
    k_match<<<g1, 256>>>(priors, boxes, B, P, O);

    dim3 g2((P + LTILE - 1) / LTILE, B);
    size_t smem = (size_t)LTILE * C * sizeof(float);
    k_loss<<<g2, LTHREADS, smem>>>(loc, conf, priors, boxes, labels, B, P, O, C);

    k_mine<<<B, MTPB>>>((float*)d_out, B, P, O);
}

// round 7
// speedup vs baseline: 1.1614x; 1.1614x over previous
#include <cuda_runtime.h>
#include <math.h>

#define MAXB 32
#define MAXP 24564
#define MAXO 32
#define LTILE 32             // rows per k_loss block
#define LTHREADS 128         // 4 threads per row
#define MTPB 1024
#define MVPT 24              // ceil(24564/1024)

// ---------------- scratch (zero-initialized at load; self-cleaning) -----------
__device__ int                d_m  [MAXB * MAXP];    // idx | (pos?32:0)
__device__ float              d_lc [MAXB * MAXP];    // negative CE (0 for positives)
__device__ unsigned long long d_bp [MAXB * MAXO];    // (iou_bits, ~p) best prior per truth
__device__ double             g_loss_l;
__device__ double             g_loss_c;
__device__ int                g_num_pos[MAXB];
__device__ int                g_done;

// ---------------- helpers ------------------------------------------------------
__device__ __forceinline__ unsigned int su32(const void* p) {
    unsigned int a;
    asm("{ .reg .u64 t; cvta.to.shared.u64 t, %1; cvt.u32.u64 %0, t; }" : "=r"(a) : "l"(p));
    return a;
}
__device__ __forceinline__ void mbar_init(unsigned int mbar, unsigned int cnt) {
    asm volatile("mbarrier.init.shared.b64 [%0], %1;" :: "r"(mbar), "r"(cnt) : "memory");
}
__device__ __forceinline__ void mbar_expect_tx(unsigned int mbar, unsigned int bytes) {
    asm volatile("mbarrier.arrive.expect_tx.shared.b64 _, [%0], %1;" :: "r"(mbar), "r"(bytes) : "memory");
}
__device__ __forceinline__ void bulk_g2s(unsigned int dst, const void* src,
                                         unsigned int bytes, unsigned int mbar) {
    asm volatile(
        "cp.async.bulk.shared::cta.global.mbarrier::complete_tx::bytes [%0], [%1], %2, [%3];"
        :: "r"(dst), "l"(src), "r"(bytes), "r"(mbar) : "memory");
}
__device__ __forceinline__ void mbar_wait(unsigned int mbar, unsigned int parity) {
    asm volatile(
        "{\n\t"
        ".reg .pred P1;\n\t"
        "WL%=:\n\t"
        "mbarrier.try_wait.parity.acquire.cta.shared::cta.b64 P1, [%0], %1, 0x989680;\n\t"
        "@P1 bra.uni WD%=;\n\t"
        "bra.uni WL%=;\n\t"
        "WD%=:\n\t"
        "}"
        :: "r"(mbar), "r"(parity) : "memory");
}

// ---------------- matching: guarded shared atomics, no REDUX --------------------
__global__ __launch_bounds__(256) void k_match(
    const float* __restrict__ priors, const float* __restrict__ boxes,
    int B, int P, int O)
{
    int b = blockIdx.y;
    int p = blockIdx.x * blockDim.x + threadIdx.x;
    bool valid = (p < P);
    int  pc = valid ? p : (P - 1);

    __shared__ float4 tb4[MAXO];
    __shared__ unsigned int sguard[MAXO];
    __shared__ unsigned long long sbp[MAXO];
    if (threadIdx.x < O) {
        tb4[threadIdx.x] = ((const float4*)boxes)[b * O + threadIdx.x];
        sguard[threadIdx.x] = 0u;
        sbp[threadIdx.x] = 0ull;
    }
    __syncthreads();

    float4 pr = ((const float4*)priors)[pc];
    float ax0 = pr.x - pr.z * 0.5f, ay0 = pr.y - pr.w * 0.5f;
    float ax1 = pr.x + pr.z * 0.5f, ay1 = pr.y + pr.w * 0.5f;
    float area_a = (ax1 - ax0) * (ay1 - ay0);

    unsigned long long mykey =
        (unsigned long long)(0xFFFFFFFFu - (unsigned)p);   // low half fixed per thread

    float best = -1.0f; int bidx = 0;
    #pragma unroll 4
    for (int o = 0; o < O; o++) {
        float4 t = tb4[o];                 // broadcast LDS.128
        float lx = fmaxf(ax0, t.x), ly = fmaxf(ay0, t.y);
        float rx = fminf(ax1, t.z), ry = fminf(ay1, t.w);
        float w = fmaxf(rx - lx, 0.0f), h = fmaxf(ry - ly, 0.0f);
        float inter = w * h;
        float area_b = (t.z - t.x) * (t.w - t.y);
        float iou = inter / (area_a + area_b - inter);   // exact div (matches ref bits)
        if (valid) {
            if (iou > best) { best = iou; bidx = o; }    // first-max (JAX argmax)
            unsigned int kb = __float_as_uint(iou);      // iou >= 0 -> monotone
            unsigned int g = *(volatile unsigned int*)&sguard[o];
            if (kb >= g && kb != 0u) {                   // guard: rare atomics only
                if (kb > g) atomicMax(&sguard[o], kb);
                atomicMax(&sbp[o], (((unsigned long long)kb) << 32) | mykey);
            }
        }
    }
    if (valid)
        d_m[(size_t)b * P + p] = bidx | ((best >= 0.5f) ? 32 : 0);
    __syncthreads();
    if (threadIdx.x < O && sbp[threadIdx.x] != 0ull)
        atomicMax(&d_bp[b * O + threadIdx.x], sbp[threadIdx.x]);
}

// ---------------- loss: bulk-async staged tile, quad-per-row ---------------------
__device__ __forceinline__ float sl1(float x) {
    float d = fabsf(x);
    return (d < 1.0f) ? 0.5f * d * d : d - 0.5f;
}

__global__ __launch_bounds__(LTHREADS, 12) void k_loss(
    const float* __restrict__ loc, const float* __restrict__ conf,
    const float* __restrict__ priors, const float* __restrict__ boxes,
    const int* __restrict__ labels, int B, int P, int O, int C)
{
    extern __shared__ float sh[];                    // LTILE*C floats
    __shared__ __align__(8) unsigned long long mbar;
    __shared__ int sbp_p[MAXO];
    __shared__ int slab [MAXO];

    int b  = blockIdx.y;
    int p0 = blockIdx.x * LTILE;
    int t  = threadIdx.x;
    int nrow = min(LTILE, P - p0);

    size_t srcOff = ((size_t)b * P + p0) * (size_t)C;
    const float* src = conf + srcOff;
    unsigned int bytes = (unsigned int)(nrow * C) * 4u;
    bool bulk_ok = ((bytes & 15u) == 0u) && (((srcOff * 4u) & 15u) == 0u);

    unsigned int mb = su32(&mbar);
    if (bulk_ok && t == 0) mbar_init(mb, 1);
    __syncthreads();
    if (bulk_ok) {
        if (t == 0) {
            mbar_expect_tx(mb, bytes);
            bulk_g2s(su32(sh), src, bytes, mb);
        }
    } else {
        for (int i = t; i < nrow * C; i += LTHREADS) sh[i] = src[i];
    }
    if (t < MAXO) {   // overlapped with the bulk copy
        if (t < O) {
            unsigned long long key = d_bp[b * O + t];
            sbp_p[t] = (int)(0xFFFFFFFFu - (unsigned)(key & 0xFFFFFFFFull)); // key==0 -> -1
            slab [t] = labels[b * O + t];
        } else { sbp_p[t] = -1; slab[t] = 0; }
    }
    if (bulk_ok) mbar_wait(mb, 0);
    __syncthreads();

    // quad-per-row exp sums
    int r = t >> 2, q = t & 3;
    int h = (C + 3) >> 2;
    int c0 = q * h, c1 = min(c0 + h, C);
    float s0 = 0.f, s1 = 0.f, s2 = 0.f, s3 = 0.f;
    if (r < nrow) {
        const float* row = sh + r * C;
        int c = c0;
        for (; c + 3 < c1; c += 4) {
            s0 += __expf(row[c]);   s1 += __expf(row[c+1]);
            s2 += __expf(row[c+2]); s3 += __expf(row[c+3]);
        }
        for (; c < c1; c++) s0 += __expf(row[c]);
    }
    float s = (s0 + s1) + (s2 + s3);
    s += __shfl_xor_sync(0xffffffffu, s, 1);
    s += __shfl_xor_sync(0xffffffffu, s, 2);

    if (q != 0 || r >= nrow) return;
    int p = p0 + r;
    float lse = __logf(s);

    size_t bp = (size_t)b * P + p;
    int m   = d_m[bp];
    int idx = m & 31;
    bool pos = (m & 32) != 0;
    #pragma unroll
    for (int o = 0; o < MAXO; o++)          // sequential -> last writer wins
        if (sbp_p[o] == p) { idx = o; pos = true; }

    int   cls = pos ? slab[idx] : 0;
    float ce  = lse - sh[r * C + cls];
    d_lc[bp] = pos ? 0.0f : ce;
    if (pos) {
        atomicAdd(&g_loss_c, (double)ce);
        atomicAdd(&g_num_pos[b], 1);
        float4 tr = ((const float4*)boxes)[b * O + idx];
        float4 pv = ((const float4*)priors)[p];
        float gx = ((tr.x + tr.z) * 0.5f - pv.x) / (0.1f * pv.z);
        float gy = ((tr.y + tr.w) * 0.5f - pv.y) / (0.1f * pv.w);
        float gw = logf((tr.z - tr.x) / pv.z) / 0.2f;
        float gh = logf((tr.w - tr.y) / pv.w) / 0.2f;
        float4 lp = ((const float4*)loc)[bp];
        float l = sl1(lp.x - gx) + sl1(lp.y - gy) + sl1(lp.z - gw) + sl1(lp.w - gh);
        atomicAdd(&g_loss_l, (double)l);
    }
}

// ---------------- mining: per-warp-hist radix select + finalize + reset ---------
__global__ __launch_bounds__(MTPB) void k_mine(float* out, int B, int P, int O) {
    int b = blockIdx.x;
    const float* lc = d_lc + (size_t)b * P;
    int lane = threadIdx.x & 31;
    int wid  = threadIdx.x >> 5;

    __shared__ unsigned int histw[32 * 256];   // per-warp histograms
    __shared__ unsigned int hist[256];
    __shared__ unsigned int s_prefix;
    __shared__ int s_remaining;
    __shared__ double sred[MTPB / 32];

    // early reset of d_bp for the next replay (k_loss already consumed it)
    if (threadIdx.x < O) d_bp[b * O + threadIdx.x] = 0ull;

    int np = g_num_pos[b];
    long long K64 = 3LL * np;
    if (K64 > P - 1) K64 = P - 1;
    int K = (int)K64;

    if (K > 0) {
        unsigned int keys[MVPT];
        #pragma unroll
        for (int v = 0; v < MVPT; v++) {
            int p = v * MTPB + threadIdx.x;
            keys[v] = (p < P) ? __float_as_uint(lc[p]) : 0u;
        }

        if (threadIdx.x == 0) { s_prefix = 0u; s_remaining = K; }
        __syncthreads();

        for (int pass = 3; pass >= 0; pass--) {
            int shift = pass * 8;
            #pragma unroll
            for (int i = 0; i < 8; i++) histw[i * MTPB + threadIdx.x] = 0u;
            __syncthreads();
            unsigned int prefix = s_prefix;
            #pragma unroll
            for (int v = 0; v < MVPT; v++) {
                int p = v * MTPB + threadIdx.x;
                unsigned int key = keys[v];
                bool match = (p < P) &&
                    ((pass == 3) || ((key >> (shift + 8)) == (prefix >> (shift + 8))));
                unsigned int bin = (key >> shift) & 0xFFu;
                unsigned int grp = __match_any_sync(0xffffffffu, match ? bin : 0x100u);
                if (match && lane == (__ffs(grp) - 1))
                    atomicAdd(&histw[(wid << 8) | bin], __popc(grp));
            }
            __syncthreads();
            if (threadIdx.x < 256) {            // merge per-warp hists (conflict-free)
                unsigned int sum = 0;
                #pragma unroll
                for (int w = 0; w < 32; w++) sum += histw[w * 256 + threadIdx.x];
                hist[threadIdx.x] = sum;
            }
            __syncthreads();
            if (wid == 0) {  // parallel descending scan of 256 bins
                int start = 255 - 8 * lane;
                unsigned int hh[8]; unsigned int tot = 0;
                #pragma unroll
                for (int j = 0; j < 8; j++) { hh[j] = hist[start - j]; tot += hh[j]; }
                unsigned int pre = tot;
                #pragma unroll
                for (int off = 1; off < 32; off <<= 1) {
                    unsigned int tt = __shfl_up_sync(0xffffffffu, pre, off);
                    if (lane >= off) pre += tt;
                }
                pre -= tot;
                unsigned int rem = (unsigned)s_remaining;
                if (pre < rem && pre + tot >= rem) {
                    unsigned int cum = pre;
                    #pragma unroll
                    for (int j = 0; j < 8; j++) {
                        if (cum + hh[j] >= rem) {
                            s_prefix = prefix | ((unsigned)(start - j) << shift);
                            s_remaining = (int)(rem - cum);
                            break;
                        }
                        cum += hh[j];
                    }
                }
            }
            __syncthreads();
        }

        unsigned int tau = s_prefix;
        int remaining = s_remaining;
        double part = 0.0;
        #pragma unroll
        for (int v = 0; v < MVPT; v++)
            if (keys[v] > tau) part += (double)__uint_as_float(keys[v]);
        #pragma unroll
        for (int off = 16; off; off >>= 1)
            part += __shfl_xor_sync(0xffffffffu, part, off);
        if (lane == 0) sred[wid] = part;
        __syncthreads();
        if (wid == 0) {
            double tt = (lane < MTPB / 32) ? sred[lane] : 0.0;
            #pragma unroll
            for (int off = 16; off; off >>= 1)
                tt += __shfl_xor_sync(0xffffffffu, tt, off);
            if (lane == 0)
                atomicAdd(&g_loss_c, tt + (double)remaining * (double)__uint_as_float(tau));
        }
    }

    // finalize: last block writes the output and resets globals for the next replay
    __syncthreads();
    if (threadIdx.x == 0) {
        __threadfence();
        if (atomicAdd(&g_done, 1) == B - 1) {
            double N = 0.0;
            for (int i = 0; i < B; i++) N += (double)g_num_pos[i];
            float Nf = (float)N;
            out[0] = (float)g_loss_l / Nf + (float)g_loss_c / Nf;
            g_loss_l = 0.0; g_loss_c = 0.0; g_done = 0;
            for (int i = 0; i < B; i++) g_num_pos[i] = 0;
        }
    }
}

// ---------------- launch -----------------------------------------------------------
extern "C" void kernel_launch(void* const* d_in, const int* in_sizes, int n_in,
                              void* d_out, int out_size)
{
    const float* loc    = (const float*)d_in[0];
    const float* conf   = (const float*)d_in[1];
    const float* priors = (const float*)d_in[2];
    const float* boxes  = (const float*)d_in[3];
    const int*   labels = (const int*)  d_in[4];

    int P = in_sizes[2] / 4;
    int B = in_sizes[0] / (P * 4);
    int C = (int)((long long)in_sizes[1] / ((long long)B * P));
    int O = in_sizes[4] / B;

    dim3 g1((P + 255) / 256, B);
    k_match<<<g1, 256>>>(priors, boxes, B, P, O);

    dim3 g2((P + LTILE - 1) / LTILE, B);
    size_t smem = (size_t)LTILE * C * sizeof(float);
    k_loss<<<g2, LTHREADS, smem>>>(loc, conf, priors, boxes, labels, B, P, O, C);

    k_mine<<<B, MTPB>>>((float*)d_out, B, P, O);
}

// round 8
// speedup vs baseline: 1.3986x; 1.2043x over previous
#include <cuda_runtime.h>
#include <math.h>

#define MAXB 32
#define MAXP 24564
#define MAXO 32
#define LTILE 32             // rows per k_loss block
#define LTHREADS 128         // 4 threads per row
#define MTPB 1024
#define MVPT 24              // ceil(24564/1024)
#define ACHUNK 1024          // priors per k_argmax block

// ---------------- scratch (zero-initialized at load; self-cleaning) -----------
__device__ int                d_m  [MAXB * MAXP];    // idx | (pos?32:0)
__device__ float              d_lc [MAXB * MAXP];    // negative CE (0 for positives)
__device__ unsigned long long d_bp [MAXB * MAXO];    // (iou_bits, ~p) best prior per truth
__device__ double             g_loss_l;
__device__ double             g_loss_c;
__device__ int                g_num_pos[MAXB];
__device__ int                g_done;

// ---------------- helpers ------------------------------------------------------
__device__ __forceinline__ unsigned int su32(const void* p) {
    unsigned int a;
    asm("{ .reg .u64 t; cvta.to.shared.u64 t, %1; cvt.u32.u64 %0, t; }" : "=r"(a) : "l"(p));
    return a;
}
__device__ __forceinline__ void mbar_init(unsigned int mbar, unsigned int cnt) {
    asm volatile("mbarrier.init.shared.b64 [%0], %1;" :: "r"(mbar), "r"(cnt) : "memory");
}
__device__ __forceinline__ void mbar_expect_tx(unsigned int mbar, unsigned int bytes) {
    asm volatile("mbarrier.arrive.expect_tx.shared.b64 _, [%0], %1;" :: "r"(mbar), "r"(bytes) : "memory");
}
__device__ __forceinline__ void bulk_g2s(unsigned int dst, const void* src,
                                         unsigned int bytes, unsigned int mbar) {
    asm volatile(
        "cp.async.bulk.shared::cta.global.mbarrier::complete_tx::bytes [%0], [%1], %2, [%3];"
        :: "r"(dst), "l"(src), "r"(bytes), "r"(mbar) : "memory");
}
__device__ __forceinline__ void mbar_wait(unsigned int mbar, unsigned int parity) {
    asm volatile(
        "{\n\t"
        ".reg .pred P1;\n\t"
        "WL%=:\n\t"
        "mbarrier.try_wait.parity.acquire.cta.shared::cta.b64 P1, [%0], %1, 0x989680;\n\t"
        "@P1 bra.uni WD%=;\n\t"
        "bra.uni WL%=;\n\t"
        "WD%=:\n\t"
        "}"
        :: "r"(mbar), "r"(parity) : "memory");
}

// ---------------- per-prior argmax over truths: cross-mult, div-free ------------
__global__ __launch_bounds__(256) void k_match(
    const float* __restrict__ priors, const float* __restrict__ boxes,
    int B, int P, int O)
{
    int b = blockIdx.y;
    int p = blockIdx.x * blockDim.x + threadIdx.x;
    bool valid = (p < P);
    int  pc = valid ? p : (P - 1);

    __shared__ float4 tb4[MAXO];
    __shared__ float  sarea[MAXO];
    if (threadIdx.x < O) {
        float4 t = ((const float4*)boxes)[b * O + threadIdx.x];
        tb4[threadIdx.x] = t;
        sarea[threadIdx.x] = (t.z - t.x) * (t.w - t.y);
    }
    __syncthreads();

    float4 pr = ((const float4*)priors)[pc];
    float ax0 = pr.x - pr.z * 0.5f, ay0 = pr.y - pr.w * 0.5f;
    float ax1 = pr.x + pr.z * 0.5f, ay1 = pr.y + pr.w * 0.5f;
    float area_a = (ax1 - ax0) * (ay1 - ay0);

    float ibest = 0.0f, dbest = 1.0f; int bidx = 0;
    #pragma unroll 8
    for (int o = 0; o < O; o++) {
        float4 t = tb4[o];                 // broadcast LDS.128
        float areab = sarea[o];
        float lx = fmaxf(ax0, t.x), ly = fmaxf(ay0, t.y);
        float rx = fminf(ax1, t.z), ry = fminf(ay1, t.w);
        float w = fmaxf(rx - lx, 0.0f), h = fmaxf(ry - ly, 0.0f);
        float inter = w * h;
        float den = (area_a + areab) - inter;    // > 0 always
        // argmax via cross-multiplication (strict > keeps first index)
        if (inter * dbest > ibest * den) { ibest = inter; dbest = den; bidx = o; }
    }
    if (valid) {
        bool pos = (2.0f * ibest >= dbest);      // iou >= 0.5
        d_m[(size_t)b * P + p] = bidx | (pos ? 32 : 0);
    }
}

// ---------------- per-truth argmax over priors: lane = truth --------------------
__global__ __launch_bounds__(1024) void k_argmax(
    const float* __restrict__ priors, const float* __restrict__ boxes,
    int B, int P, int O)
{
    __shared__ float4 sp[ACHUNK];                // 16KB; reused for combine
    int b  = blockIdx.y;
    int base = blockIdx.x * ACHUNK;
    int n  = min(ACHUNK, P - base);
    int w  = threadIdx.x >> 5, l = threadIdx.x & 31;

    // truth box in registers, one per lane
    int lo = (l < O) ? l : 0;
    float4 t = ((const float4*)boxes)[b * O + lo];
    float areab = (t.z - t.x) * (t.w - t.y);

    // stage priors chunk
    for (int i = threadIdx.x; i < n; i += 1024)
        sp[i] = ((const float4*)priors)[base + i];
    __syncthreads();

    // warp w streams priors [w*32, w*32+32); all lanes same prior, lane-truth IoU
    int s = w * 32, e = min(s + 32, n);
    float ibest = 0.0f, dbest = 1.0f; int pbest = base + s;
    for (int i = s; i < e; i++) {
        float4 pr = sp[i];                        // broadcast LDS.128
        float ax0 = pr.x - pr.z * 0.5f, ay0 = pr.y - pr.w * 0.5f;
        float ax1 = pr.x + pr.z * 0.5f, ay1 = pr.y + pr.w * 0.5f;
        float area_a = (ax1 - ax0) * (ay1 - ay0);
        float lx = fmaxf(ax0, t.x), ly = fmaxf(ay0, t.y);
        float rx = fminf(ax1, t.z), ry = fminf(ay1, t.w);
        float ww = fmaxf(rx - lx, 0.0f), hh = fmaxf(ry - ly, 0.0f);
        float inter = ww * hh;
        float den = (area_a + areab) - inter;
        if (inter * dbest > ibest * den) { ibest = inter; dbest = den; pbest = base + i; }
    }
    __syncthreads();

    // combine across warps (reuse sp as scratch: 3 x 4KB)
    float* ci = (float*)sp;
    float* cd = ci + ACHUNK;
    int*   cp = (int*)(cd + ACHUNK);
    if (l < O) {
        ci[w * 32 + l] = ibest;
        cd[w * 32 + l] = dbest;
        cp[w * 32 + l] = pbest;
    }
    __syncthreads();
    if (threadIdx.x < (unsigned)O) {
        int o = threadIdx.x;
        float bi = ci[o], bd = cd[o]; int bp_ = cp[o];
        #pragma unroll 8
        for (int w2 = 1; w2 < 32; w2++) {
            float i2 = ci[w2 * 32 + o], d2 = cd[w2 * 32 + o];
            if (i2 * bd > bi * d2) { bi = i2; bd = d2; bp_ = cp[w2 * 32 + o]; }
        }
        float iou = bi / bd;                     // exact IEEE div: matches ref bits
        unsigned long long key =
            (((unsigned long long)__float_as_uint(iou)) << 32) |
            (unsigned long long)(0xFFFFFFFFu - (unsigned)bp_);
        atomicMax(&d_bp[b * O + o], key);
    }
}

// ---------------- loss: bulk-async staged tile, quad-per-row ---------------------
__device__ __forceinline__ float sl1(float x) {
    float d = fabsf(x);
    return (d < 1.0f) ? 0.5f * d * d : d - 0.5f;
}

__global__ __launch_bounds__(LTHREADS, 12) void k_loss(
    const float* __restrict__ loc, const float* __restrict__ conf,
    const float* __restrict__ priors, const float* __restrict__ boxes,
    const int* __restrict__ labels, int B, int P, int O, int C)
{
    extern __shared__ float sh[];                    // LTILE*C floats
    __shared__ __align__(8) unsigned long long mbar;
    __shared__ int sbp_p[MAXO];
    __shared__ int slab [MAXO];

    int b  = blockIdx.y;
    int p0 = blockIdx.x * LTILE;
    int t  = threadIdx.x;
    int nrow = min(LTILE, P - p0);

    size_t srcOff = ((size_t)b * P + p0) * (size_t)C;
    const float* src = conf + srcOff;
    unsigned int bytes = (unsigned int)(nrow * C) * 4u;
    bool bulk_ok = ((bytes & 15u) == 0u) && (((srcOff * 4u) & 15u) == 0u);

    unsigned int mb = su32(&mbar);
    if (bulk_ok && t == 0) mbar_init(mb, 1);
    __syncthreads();
    if (bulk_ok) {
        if (t == 0) {
            mbar_expect_tx(mb, bytes);
            bulk_g2s(su32(sh), src, bytes, mb);
        }
    } else {
        for (int i = t; i < nrow * C; i += LTHREADS) sh[i] = src[i];
    }
    if (t < MAXO) {   // overlapped with the bulk copy
        if (t < O) {
            unsigned long long key = d_bp[b * O + t];
            sbp_p[t] = (int)(0xFFFFFFFFu - (unsigned)(key & 0xFFFFFFFFull));
            slab [t] = labels[b * O + t];
        } else { sbp_p[t] = -1; slab[t] = 0; }
    }
    if (bulk_ok) mbar_wait(mb, 0);
    __syncthreads();

    // quad-per-row exp sums
    int r = t >> 2, q = t & 3;
    int h = (C + 3) >> 2;
    int c0 = q * h, c1 = min(c0 + h, C);
    float s0 = 0.f, s1 = 0.f, s2 = 0.f, s3 = 0.f;
    if (r < nrow) {
        const float* row = sh + r * C;
        int c = c0;
        for (; c + 3 < c1; c += 4) {
            s0 += __expf(row[c]);   s1 += __expf(row[c+1]);
            s2 += __expf(row[c+2]); s3 += __expf(row[c+3]);
        }
        for (; c < c1; c++) s0 += __expf(row[c]);
    }
    float s = (s0 + s1) + (s2 + s3);
    s += __shfl_xor_sync(0xffffffffu, s, 1);
    s += __shfl_xor_sync(0xffffffffu, s, 2);

    if (q != 0 || r >= nrow) return;
    int p = p0 + r;
    float lse = __logf(s);

    size_t bp = (size_t)b * P + p;
    int m   = d_m[bp];
    int idx = m & 31;
    bool pos = (m & 32) != 0;
    #pragma unroll
    for (int o = 0; o < MAXO; o++)          // sequential -> last writer wins
        if (sbp_p[o] == p) { idx = o; pos = true; }

    int   cls = pos ? slab[idx] : 0;
    float ce  = lse - sh[r * C + cls];
    d_lc[bp] = pos ? 0.0f : ce;
    if (pos) {
        atomicAdd(&g_loss_c, (double)ce);
        atomicAdd(&g_num_pos[b], 1);
        float4 tr = ((const float4*)boxes)[b * O + idx];
        float4 pv = ((const float4*)priors)[p];
        float gx = ((tr.x + tr.z) * 0.5f - pv.x) / (0.1f * pv.z);
        float gy = ((tr.y + tr.w) * 0.5f - pv.y) / (0.1f * pv.w);
        float gw = logf((tr.z - tr.x) / pv.z) / 0.2f;
        float gh = logf((tr.w - tr.y) / pv.w) / 0.2f;
        float4 lp = ((const float4*)loc)[bp];
        float l = sl1(lp.x - gx) + sl1(lp.y - gy) + sl1(lp.z - gw) + sl1(lp.w - gh);
        atomicAdd(&g_loss_l, (double)l);
    }
}

// ---------------- mining: per-warp-hist radix select + finalize + reset ---------
__global__ __launch_bounds__(MTPB) void k_mine(float* out, int B, int P, int O) {
    int b = blockIdx.x;
    const float* lc = d_lc + (size_t)b * P;
    int lane = threadIdx.x & 31;
    int wid  = threadIdx.x >> 5;

    __shared__ unsigned int histw[32 * 256];   // per-warp histograms
    __shared__ unsigned int hist[256];
    __shared__ unsigned int s_prefix;
    __shared__ int s_remaining;
    __shared__ double sred[MTPB / 32];

    // early reset of d_bp for the next replay (k_loss already consumed it)
    if (threadIdx.x < O) d_bp[b * O + threadIdx.x] = 0ull;

    int np = g_num_pos[b];
    long long K64 = 3LL * np;
    if (K64 > P - 1) K64 = P - 1;
    int K = (int)K64;

    if (K > 0) {
        unsigned int keys[MVPT];
        #pragma unroll
        for (int v = 0; v < MVPT; v++) {
            int p = v * MTPB + threadIdx.x;
            keys[v] = (p < P) ? __float_as_uint(lc[p]) : 0u;
        }

        if (threadIdx.x == 0) { s_prefix = 0u; s_remaining = K; }
        __syncthreads();

        for (int pass = 3; pass >= 0; pass--) {
            int shift = pass * 8;
            #pragma unroll
            for (int i = 0; i < 8; i++) histw[i * MTPB + threadIdx.x] = 0u;
            __syncthreads();
            unsigned int prefix = s_prefix;
            #pragma unroll
            for (int v = 0; v < MVPT; v++) {
                int p = v * MTPB + threadIdx.x;
                unsigned int key = keys[v];
                bool match = (p < P) &&
                    ((pass == 3) || ((key >> (shift + 8)) == (prefix >> (shift + 8))));
                unsigned int bin = (key >> shift) & 0xFFu;
                unsigned int grp = __match_any_sync(0xffffffffu, match ? bin : 0x100u);
                if (match && lane == (__ffs(grp) - 1))
                    atomicAdd(&histw[(wid << 8) | bin], __popc(grp));
            }
            __syncthreads();
            if (threadIdx.x < 256) {            // merge per-warp hists (conflict-free)
                unsigned int sum = 0;
                #pragma unroll
                for (int w = 0; w < 32; w++) sum += histw[w * 256 + threadIdx.x];
                hist[threadIdx.x] = sum;
            }
            __syncthreads();
            if (wid == 0) {  // parallel descending scan of 256 bins
                int start = 255 - 8 * lane;
                unsigned int hh[8]; unsigned int tot = 0;
                #pragma unroll
                for (int j = 0; j < 8; j++) { hh[j] = hist[start - j]; tot += hh[j]; }
                unsigned int pre = tot;
                #pragma unroll
                for (int off = 1; off < 32; off <<= 1) {
                    unsigned int tt = __shfl_up_sync(0xffffffffu, pre, off);
                    if (lane >= off) pre += tt;
                }
                pre -= tot;
                unsigned int rem = (unsigned)s_remaining;
                if (pre < rem && pre + tot >= rem) {
                    unsigned int cum = pre;
                    #pragma unroll
                    for (int j = 0; j < 8; j++) {
                        if (cum + hh[j] >= rem) {
                            s_prefix = prefix | ((unsigned)(start - j) << shift);
                            s_remaining = (int)(rem - cum);
                            break;
                        }
                        cum += hh[j];
                    }
                }
            }
            __syncthreads();
        }

        unsigned int tau = s_prefix;
        int remaining = s_remaining;
        double part = 0.0;
        #pragma unroll
        for (int v = 0; v < MVPT; v++)
            if (keys[v] > tau) part += (double)__uint_as_float(keys[v]);
        #pragma unroll
        for (int off = 16; off; off >>= 1)
            part += __shfl_xor_sync(0xffffffffu, part, off);
        if (lane == 0) sred[wid] = part;
        __syncthreads();
        if (wid == 0) {
            double tt = (lane < MTPB / 32) ? sred[lane] : 0.0;
            #pragma unroll
            for (int off = 16; off; off >>= 1)
                tt += __shfl_xor_sync(0xffffffffu, tt, off);
            if (lane == 0)
                atomicAdd(&g_loss_c, tt + (double)remaining * (double)__uint_as_float(tau));
        }
    }

    // finalize: last block writes the output and resets globals for the next replay
    __syncthreads();
    if (threadIdx.x == 0) {
        __threadfence();
        if (atomicAdd(&g_done, 1) == B - 1) {
            double N = 0.0;
            for (int i = 0; i < B; i++) N += (double)g_num_pos[i];
            float Nf = (float)N;
            out[0] = (float)g_loss_l / Nf + (float)g_loss_c / Nf;
            g_loss_l = 0.0; g_loss_c = 0.0; g_done = 0;
            for (int i = 0; i < B; i++) g_num_pos[i] = 0;
        }
    }
}

// ---------------- launch -----------------------------------------------------------
extern "C" void kernel_launch(void* const* d_in, const int* in_sizes, int n_in,
                              void* d_out, int out_size)
{
    const float* loc    = (const float*)d_in[0];
    const float* conf   = (const float*)d_in[1];
    const float* priors = (const float*)d_in[2];
    const float* boxes  = (const float*)d_in[3];
    const int*   labels = (const int*)  d_in[4];

    int P = in_sizes[2] / 4;
    int B = in_sizes[0] / (P * 4);
    int C = (int)((long long)in_sizes[1] / ((long long)B * P));
    int O = in_sizes[4] / B;

    dim3 g1((P + 255) / 256, B);
    k_match<<<g1, 256>>>(priors, boxes, B, P, O);

    dim3 ga((P + ACHUNK - 1) / ACHUNK, B);
    k_argmax<<<ga, 1024>>>(priors, boxes, B, P, O);

    dim3 g2((P + LTILE - 1) / LTILE, B);
    size_t smem = (size_t)LTILE * C * sizeof(float);
    k_loss<<<g2, LTHREADS, smem>>>(loc, conf, priors, boxes, labels, B, P, O, C);

    k_mine<<<B, MTPB>>>((float*)d_out, B, P, O);
}

// round 9
// speedup vs baseline: 1.6305x; 1.1658x over previous
#include <cuda_runtime.h>
#include <math.h>

#define MAXB 32
#define MAXP 24564
#define MAXO 32
#define LTILE 32             // rows per k_loss block
#define LTHREADS 128         // 4 threads per row
#define MTPB 1024
#define MVPT 24              // ceil(24564/1024)
#define ACHUNK 1024          // priors per k_argmax block

// ---------------- scratch (zero-initialized at load; self-cleaning) -----------
__device__ int                d_m  [MAXB * MAXP];    // idx | (pos?32:0)
__device__ float              d_lc [MAXB * MAXP];    // negative CE (0 for positives)
__device__ unsigned long long d_bp [MAXB * MAXO];    // (iou_bits, ~p) best prior per truth
__device__ unsigned int       d_hist[MAXB * 256];    // top-byte histogram of d_lc
__device__ double             g_loss_l;
__device__ double             g_loss_c;
__device__ int                g_num_pos[MAXB];
__device__ int                g_done;

// ---------------- helpers ------------------------------------------------------
__device__ __forceinline__ unsigned int su32(const void* p) {
    unsigned int a;
    asm("{ .reg .u64 t; cvta.to.shared.u64 t, %1; cvt.u32.u64 %0, t; }" : "=r"(a) : "l"(p));
    return a;
}
__device__ __forceinline__ void mbar_init(unsigned int mbar, unsigned int cnt) {
    asm volatile("mbarrier.init.shared.b64 [%0], %1;" :: "r"(mbar), "r"(cnt) : "memory");
}
__device__ __forceinline__ void mbar_expect_tx(unsigned int mbar, unsigned int bytes) {
    asm volatile("mbarrier.arrive.expect_tx.shared.b64 _, [%0], %1;" :: "r"(mbar), "r"(bytes) : "memory");
}
__device__ __forceinline__ void bulk_g2s(unsigned int dst, const void* src,
                                         unsigned int bytes, unsigned int mbar) {
    asm volatile(
        "cp.async.bulk.shared::cta.global.mbarrier::complete_tx::bytes [%0], [%1], %2, [%3];"
        :: "r"(dst), "l"(src), "r"(bytes), "r"(mbar) : "memory");
}
__device__ __forceinline__ void mbar_wait(unsigned int mbar, unsigned int parity) {
    asm volatile(
        "{\n\t"
        ".reg .pred P1;\n\t"
        "WL%=:\n\t"
        "mbarrier.try_wait.parity.acquire.cta.shared::cta.b64 P1, [%0], %1, 0x989680;\n\t"
        "@P1 bra.uni WD%=;\n\t"
        "bra.uni WL%=;\n\t"
        "WD%=:\n\t"
        "}"
        :: "r"(mbar), "r"(parity) : "memory");
}

// ---------------- per-prior argmax over truths: cross-mult, div-free ------------
__global__ __launch_bounds__(256) void k_match(
    const float* __restrict__ priors, const float* __restrict__ boxes,
    int B, int P, int O)
{
    int b = blockIdx.y;
    int p = blockIdx.x * blockDim.x + threadIdx.x;
    bool valid = (p < P);
    int  pc = valid ? p : (P - 1);

    __shared__ float4 tb4[MAXO];
    __shared__ float  sarea[MAXO];
    if (threadIdx.x < O) {
        float4 t = ((const float4*)boxes)[b * O + threadIdx.x];
        tb4[threadIdx.x] = t;
        sarea[threadIdx.x] = (t.z - t.x) * (t.w - t.y);
    }
    __syncthreads();

    float4 pr = ((const float4*)priors)[pc];
    float ax0 = pr.x - pr.z * 0.5f, ay0 = pr.y - pr.w * 0.5f;
    float ax1 = pr.x + pr.z * 0.5f, ay1 = pr.y + pr.w * 0.5f;
    float area_a = (ax1 - ax0) * (ay1 - ay0);

    float ibest = 0.0f, dbest = 1.0f; int bidx = 0;
    #pragma unroll 8
    for (int o = 0; o < O; o++) {
        float4 t = tb4[o];                 // broadcast LDS.128
        float areab = sarea[o];
        float lx = fmaxf(ax0, t.x), ly = fmaxf(ay0, t.y);
        float rx = fminf(ax1, t.z), ry = fminf(ay1, t.w);
        float w = fmaxf(rx - lx, 0.0f), h = fmaxf(ry - ly, 0.0f);
        float inter = w * h;
        float den = (area_a + areab) - inter;    // > 0 always
        // argmax via cross-multiplication (strict > keeps first index)
        if (inter * dbest > ibest * den) { ibest = inter; dbest = den; bidx = o; }
    }
    if (valid) {
        bool pos = (2.0f * ibest >= dbest);      // iou >= 0.5
        d_m[(size_t)b * P + p] = bidx | (pos ? 32 : 0);
    }
}

// ---------------- per-truth argmax over priors: lane = truth --------------------
__global__ __launch_bounds__(1024) void k_argmax(
    const float* __restrict__ priors, const float* __restrict__ boxes,
    int B, int P, int O)
{
    __shared__ float4 sp[ACHUNK];                // 16KB; reused for combine
    int b  = blockIdx.y;
    int base = blockIdx.x * ACHUNK;
    int n  = min(ACHUNK, P - base);
    int w  = threadIdx.x >> 5, l = threadIdx.x & 31;

    int lo = (l < O) ? l : 0;
    float4 t = ((const float4*)boxes)[b * O + lo];
    float areab = (t.z - t.x) * (t.w - t.y);

    for (int i = threadIdx.x; i < n; i += 1024)
        sp[i] = ((const float4*)priors)[base + i];
    __syncthreads();

    int s = w * 32, e = min(s + 32, n);
    float ibest = 0.0f, dbest = 1.0f; int pbest = base + s;
    for (int i = s; i < e; i++) {
        float4 pr = sp[i];                        // broadcast LDS.128
        float ax0 = pr.x - pr.z * 0.5f, ay0 = pr.y - pr.w * 0.5f;
        float ax1 = pr.x + pr.z * 0.5f, ay1 = pr.y + pr.w * 0.5f;
        float area_a = (ax1 - ax0) * (ay1 - ay0);
        float lx = fmaxf(ax0, t.x), ly = fmaxf(ay0, t.y);
        float rx = fminf(ax1, t.z), ry = fminf(ay1, t.w);
        float ww = fmaxf(rx - lx, 0.0f), hh = fmaxf(ry - ly, 0.0f);
        float inter = ww * hh;
        float den = (area_a + areab) - inter;
        if (inter * dbest > ibest * den) { ibest = inter; dbest = den; pbest = base + i; }
    }
    __syncthreads();

    float* ci = (float*)sp;
    float* cd = ci + ACHUNK;
    int*   cp = (int*)(cd + ACHUNK);
    if (l < O) {
        ci[w * 32 + l] = ibest;
        cd[w * 32 + l] = dbest;
        cp[w * 32 + l] = pbest;
    }
    __syncthreads();
    if (threadIdx.x < (unsigned)O) {
        int o = threadIdx.x;
        float bi = ci[o], bd = cd[o]; int bp_ = cp[o];
        #pragma unroll 8
        for (int w2 = 1; w2 < 32; w2++) {
            float i2 = ci[w2 * 32 + o], d2 = cd[w2 * 32 + o];
            if (i2 * bd > bi * d2) { bi = i2; bd = d2; bp_ = cp[w2 * 32 + o]; }
        }
        float iou = bi / bd;                     // exact IEEE div: matches ref bits
        unsigned long long key =
            (((unsigned long long)__float_as_uint(iou)) << 32) |
            (unsigned long long)(0xFFFFFFFFu - (unsigned)bp_);
        atomicMax(&d_bp[b * O + o], key);
    }
}

// ---------------- loss: bulk-async staged tile + top-byte hist accumulation -----
__device__ __forceinline__ float sl1(float x) {
    float d = fabsf(x);
    return (d < 1.0f) ? 0.5f * d * d : d - 0.5f;
}

__global__ __launch_bounds__(LTHREADS, 12) void k_loss(
    const float* __restrict__ loc, const float* __restrict__ conf,
    const float* __restrict__ priors, const float* __restrict__ boxes,
    const int* __restrict__ labels, int B, int P, int O, int C)
{
    extern __shared__ float sh[];                    // LTILE*C floats
    __shared__ __align__(8) unsigned long long mbar;
    __shared__ int sbp_p[MAXO];
    __shared__ int slab [MAXO];

    int b  = blockIdx.y;
    int p0 = blockIdx.x * LTILE;
    int t  = threadIdx.x;
    int nrow = min(LTILE, P - p0);

    size_t srcOff = ((size_t)b * P + p0) * (size_t)C;
    const float* src = conf + srcOff;
    unsigned int bytes = (unsigned int)(nrow * C) * 4u;
    bool bulk_ok = ((bytes & 15u) == 0u) && (((srcOff * 4u) & 15u) == 0u);

    unsigned int mb = su32(&mbar);
    if (bulk_ok && t == 0) mbar_init(mb, 1);
    __syncthreads();
    if (bulk_ok) {
        if (t == 0) {
            mbar_expect_tx(mb, bytes);
            bulk_g2s(su32(sh), src, bytes, mb);
        }
    } else {
        for (int i = t; i < nrow * C; i += LTHREADS) sh[i] = src[i];
    }
    if (t < MAXO) {   // overlapped with the bulk copy
        if (t < O) {
            unsigned long long key = d_bp[b * O + t];
            sbp_p[t] = (int)(0xFFFFFFFFu - (unsigned)(key & 0xFFFFFFFFull));
            slab [t] = labels[b * O + t];
        } else { sbp_p[t] = -1; slab[t] = 0; }
    }
    if (bulk_ok) mbar_wait(mb, 0);
    __syncthreads();

    // quad-per-row exp sums
    int r = t >> 2, q = t & 3;
    int h = (C + 3) >> 2;
    int c0 = q * h, c1 = min(c0 + h, C);
    float s0 = 0.f, s1 = 0.f, s2 = 0.f, s3 = 0.f;
    if (r < nrow) {
        const float* row = sh + r * C;
        int c = c0;
        for (; c + 3 < c1; c += 4) {
            s0 += __expf(row[c]);   s1 += __expf(row[c+1]);
            s2 += __expf(row[c+2]); s3 += __expf(row[c+3]);
        }
        for (; c < c1; c++) s0 += __expf(row[c]);
    }
    float s = (s0 + s1) + (s2 + s3);
    s += __shfl_xor_sync(0xffffffffu, s, 1);
    s += __shfl_xor_sync(0xffffffffu, s, 2);

    bool live = (q == 0) && (r < nrow);
    unsigned int lmask = __ballot_sync(0xffffffffu, live);
    unsigned int key = 0u;

    if (live) {
        int p = p0 + r;
        float lse = __logf(s);

        size_t bp = (size_t)b * P + p;
        int m   = d_m[bp];
        int idx = m & 31;
        bool pos = (m & 32) != 0;
        #pragma unroll
        for (int o = 0; o < MAXO; o++)          // sequential -> last writer wins
            if (sbp_p[o] == p) { idx = o; pos = true; }

        int   cls = pos ? slab[idx] : 0;
        float ce  = lse - sh[r * C + cls];
        float lcv = pos ? 0.0f : ce;
        d_lc[bp] = lcv;
        key = __float_as_uint(lcv);
        if (pos) {
            atomicAdd(&g_loss_c, (double)ce);
            atomicAdd(&g_num_pos[b], 1);
            float4 tr = ((const float4*)boxes)[b * O + idx];
            float4 pv = ((const float4*)priors)[p];
            float gx = ((tr.x + tr.z) * 0.5f - pv.x) / (0.1f * pv.z);
            float gy = ((tr.y + tr.w) * 0.5f - pv.y) / (0.1f * pv.w);
            float gw = logf((tr.z - tr.x) / pv.z) / 0.2f;
            float gh = logf((tr.w - tr.y) / pv.w) / 0.2f;
            float4 lp = ((const float4*)loc)[bp];
            float l = sl1(lp.x - gx) + sl1(lp.y - gy) + sl1(lp.z - gw) + sl1(lp.w - gh);
            atomicAdd(&g_loss_l, (double)l);
        }
        // warp-aggregated top-byte histogram accumulation (first radix pass)
        unsigned int bin = key >> 24;
        unsigned int grp = __match_any_sync(lmask, bin);
        if ((t & 31) == (__ffs(grp) - 1))
            atomicAdd(&d_hist[b * 256 + bin], __popc(grp));
    }
}

// ---------------- mining: hist-seeded radix select + finalize + reset -----------
__global__ __launch_bounds__(MTPB) void k_mine(float* out, int B, int P, int O) {
    int b = blockIdx.x;
    const float* lc = d_lc + (size_t)b * P;
    int lane = threadIdx.x & 31;
    int wid  = threadIdx.x >> 5;

    __shared__ unsigned int hist[256];
    __shared__ unsigned int s_prefix;
    __shared__ int s_remaining;
    __shared__ double sred[MTPB / 32];

    // resets for the next replay
    if (threadIdx.x < O) d_bp[b * O + threadIdx.x] = 0ull;
    if (threadIdx.x < 256) {
        hist[threadIdx.x] = d_hist[b * 256 + threadIdx.x];   // pass-3 hist from k_loss
        d_hist[b * 256 + threadIdx.x] = 0u;
    }

    int np = g_num_pos[b];
    long long K64 = 3LL * np;
    if (K64 > P - 1) K64 = P - 1;
    int K = (int)K64;

    if (K > 0) {
        unsigned int keys[MVPT];
        #pragma unroll
        for (int v = 0; v < MVPT; v++) {
            int p = v * MTPB + threadIdx.x;
            keys[v] = (p < P) ? __float_as_uint(lc[p]) : 0u;
        }

        if (threadIdx.x == 0) { s_prefix = 0u; s_remaining = K; }
        __syncthreads();

        // radix passes: pass 3 scans the precomputed hist; passes 2..0 scan only
        // the (rare) prefix-matching elements with warp-vote skip.
        for (int pass = 3; pass >= 0; pass--) {
            int shift = pass * 8;
            if (pass < 3) {
                if (threadIdx.x < 256) hist[threadIdx.x] = 0u;
                __syncthreads();
                unsigned int prefix = s_prefix;
                #pragma unroll
                for (int v = 0; v < MVPT; v++) {
                    int p = v * MTPB + threadIdx.x;
                    unsigned int key = keys[v];
                    bool match = (p < P) &&
                        ((key >> (shift + 8)) == (prefix >> (shift + 8)));
                    if (__any_sync(0xffffffffu, match)) {
                        if (match) atomicAdd(&hist[(key >> shift) & 0xFFu], 1u);
                    }
                }
                __syncthreads();
            }
            if (wid == 0) {  // parallel descending scan of 256 bins
                unsigned int prefix = s_prefix;
                int start = 255 - 8 * lane;
                unsigned int hh[8]; unsigned int tot = 0;
                #pragma unroll
                for (int j = 0; j < 8; j++) { hh[j] = hist[start - j]; tot += hh[j]; }
                unsigned int pre = tot;
                #pragma unroll
                for (int off = 1; off < 32; off <<= 1) {
                    unsigned int tt = __shfl_up_sync(0xffffffffu, pre, off);
                    if (lane >= off) pre += tt;
                }
                pre -= tot;
                unsigned int rem = (unsigned)s_remaining;
                if (pre < rem && pre + tot >= rem) {
                    unsigned int cum = pre;
                    #pragma unroll
                    for (int j = 0; j < 8; j++) {
                        if (cum + hh[j] >= rem) {
                            s_prefix = prefix | ((unsigned)(start - j) << shift);
                            s_remaining = (int)(rem - cum);
                            break;
                        }
                        cum += hh[j];
                    }
                }
            }
            __syncthreads();
        }

        unsigned int tau = s_prefix;
        int remaining = s_remaining;
        double part = 0.0;
        #pragma unroll
        for (int v = 0; v < MVPT; v++)
            if (keys[v] > tau) part += (double)__uint_as_float(keys[v]);
        #pragma unroll
        for (int off = 16; off; off >>= 1)
            part += __shfl_xor_sync(0xffffffffu, part, off);
        if (lane == 0) sred[wid] = part;
        __syncthreads();
        if (wid == 0) {
            double tt = (lane < MTPB / 32) ? sred[lane] : 0.0;
            #pragma unroll
            for (int off = 16; off; off >>= 1)
                tt += __shfl_xor_sync(0xffffffffu, tt, off);
            if (lane == 0)
                atomicAdd(&g_loss_c, tt + (double)remaining * (double)__uint_as_float(tau));
        }
    }

    // finalize: last block writes the output and resets globals for the next replay
    __syncthreads();
    if (threadIdx.x == 0) {
        __threadfence();
        if (atomicAdd(&g_done, 1) == B - 1) {
            double N = 0.0;
            for (int i = 0; i < B; i++) N += (double)g_num_pos[i];
            float Nf = (float)N;
            out[0] = (float)g_loss_l / Nf + (float)g_loss_c / Nf;
            g_loss_l = 0.0; g_loss_c = 0.0; g_done = 0;
            for (int i = 0; i < B; i++) g_num_pos[i] = 0;
        }
    }
}

// ---------------- launch -----------------------------------------------------------
extern "C" void kernel_launch(void* const* d_in, const int* in_sizes, int n_in,
                              void* d_out, int out_size)
{
    const float* loc    = (const float*)d_in[0];
    const float* conf   = (const float*)d_in[1];
    const float* priors = (const float*)d_in[2];
    const float* boxes  = (const float*)d_in[3];
    const int*   labels = (const int*)  d_in[4];

    int P = in_sizes[2] / 4;
    int B = in_sizes[0] / (P * 4);
    int C = (int)((long long)in_sizes[1] / ((long long)B * P));
    int O = in_sizes[4] / B;

    dim3 g1((P + 255) / 256, B);
    k_match<<<g1, 256>>>(priors, boxes, B, P, O);

    dim3 ga((P + ACHUNK - 1) / ACHUNK, B);
    k_argmax<<<ga, 1024>>>(priors, boxes, B, P, O);

    dim3 g2((P + LTILE - 1) / LTILE, B);
    size_t smem = (size_t)LTILE * C * sizeof(float);
    k_loss<<<g2, LTHREADS, smem>>>(loc, conf, priors, boxes, labels, B, P, O, C);

    k_mine<<<B, MTPB>>>((float*)d_out, B, P, O);
}